// round 1
// baseline (speedup 1.0000x reference)
#include <cuda_runtime.h>
#include <math.h>

// Problem constants (fixed by the reference)
#define BB    4096
#define KK    20
#define DN    128
#define DMEM  256
#define DT    128
#define DE    128
#define NBINS 300

// Scratch (no cudaMalloc allowed): base = src0 + nb0_mean, feat = masked mean of cat(ete, ef)
__device__ float g_base[BB * DMEM];
__device__ float g_feat[BB * DMEM];

// ---------------------------------------------------------------------------
// Kernel 1: per-source gather + masked reduction over K neighbors.
// One CTA per source b, 256 threads = one thread per output dim d.
// Warps 0-3 handle d in [0,128) (node_features / time-encoding half),
// warps 4-7 handle d in [128,256) (interval-embedding / edge-feature half),
// so the d<128 branch never diverges within a warp.
// ---------------------------------------------------------------------------
__global__ void __launch_bounds__(256) gather_reduce_kernel(
    const float* __restrict__ nodef,   // [N, 128]
    const float* __restrict__ edgef,   // [E, 128]
    const float* __restrict__ mem,     // [N, 256]
    const float* __restrict__ itab,    // [300, 128]
    const float* __restrict__ bbound,  // [301]
    const float* __restrict__ tw,      // [128]
    const float* __restrict__ tbias,   // [128]
    const float* __restrict__ ts,      // [B]
    const float* __restrict__ etimes,  // [B, K]
    const float* __restrict__ ivals,   // [B]
    const float* __restrict__ nivals,  // [B, K]
    const int*   __restrict__ srcn,    // [B]
    const int*   __restrict__ nbr,     // [B, K]
    const int*   __restrict__ eidx)    // [B, K]
{
    const int b = blockIdx.x;
    const int t = threadIdx.x;  // 0..255

    __shared__ float s_bb[NBINS + 1];
    __shared__ int   s_nb[KK];
    __shared__ int   s_ei[KK];
    __shared__ int   s_bin[KK + 1];   // [K] = neighbor bins, [K] slot = source bin
    __shared__ float s_delta[KK];
    __shared__ int   s_valid[KK];

    for (int i = t; i < NBINS + 1; i += 256) s_bb[i] = bbound[i];
    __syncthreads();

    if (t < KK) {
        int n = nbr[b * KK + t];
        s_nb[t]    = n;
        s_valid[t] = (n != -1) ? 1 : 0;
        s_ei[t]    = eidx[b * KK + t];
        s_delta[t] = ts[b] - etimes[b * KK + t];
        // searchsorted(bbound, x, side='left') - 1, clipped: exact lower_bound
        float x = nivals[b * KK + t];
        int lo = 0, hi = NBINS + 1;
        while (lo < hi) { int mid = (lo + hi) >> 1; if (s_bb[mid] < x) lo = mid + 1; else hi = mid; }
        int bin = lo - 1;
        s_bin[t] = min(max(bin, 0), NBINS - 1);
    } else if (t == KK) {
        float x = ivals[b];
        int lo = 0, hi = NBINS + 1;
        while (lo < hi) { int mid = (lo + hi) >> 1; if (s_bb[mid] < x) lo = mid + 1; else hi = mid; }
        int bin = lo - 1;
        s_bin[KK] = min(max(bin, 0), NBINS - 1);
    }
    __syncthreads();

    float cnt = 0.f;
    #pragma unroll
    for (int k = 0; k < KK; k++) cnt += (float)s_valid[k];
    cnt = fmaxf(cnt, 1.0f);
    const float inv = 1.0f / cnt;

    // src0
    const int s = srcn[b];
    float srcv = mem[(size_t)s * DMEM + t];
    if (t < DN) srcv += nodef[(size_t)s * DN + t];
    else        srcv += itab[s_bin[KK] * DN + (t - DN)];

    float w_ = 0.f, bi_ = 0.f;
    if (t < DT) { w_ = tw[t]; bi_ = tbias[t]; }

    float nbsum = 0.f, fsum = 0.f;
    #pragma unroll
    for (int k = 0; k < KK; k++) {
        if (s_valid[k]) {
            const int n = s_nb[k];
            float v = mem[(size_t)n * DMEM + t];
            if (t < DN) {
                v    += nodef[(size_t)n * DN + t];
                fsum += cosf(fmaf(s_delta[k], w_, bi_));
            } else {
                v    += itab[s_bin[k] * DN + (t - DN)];
                fsum += edgef[(size_t)s_ei[k] * DE + (t - DN)];
            }
            nbsum += v;
        }
    }

    g_base[b * DMEM + t] = srcv + nbsum * inv;
    g_feat[b * DMEM + t] = fsum * inv;     // fold /cnt into feat so GEMM output adds directly
}

// ---------------------------------------------------------------------------
// Kernel 2: out[b][d] = base[b][d] + sum_f feat[b][f] * W[f][d]
// 128 CTAs, each computes a 32(b) x 256(d) tile. Thread t owns column d=t
// with 32 accumulators; feat tile in smem, read as broadcast float4.
// ---------------------------------------------------------------------------
#define RB 32
__global__ void __launch_bounds__(256) gemm_add_kernel(
    const float* __restrict__ W,   // [256, 256] row-major (f-major)
    float*       __restrict__ out) // [B, 256]
{
    const int t  = threadIdx.x;
    const int b0 = blockIdx.x * RB;

    __shared__ float fs[RB][DMEM];  // 32 KB
    #pragma unroll
    for (int i = 0; i < RB; i++) fs[i][t] = g_feat[(b0 + i) * DMEM + t];
    __syncthreads();

    float acc[RB];
    #pragma unroll
    for (int i = 0; i < RB; i++) acc[i] = 0.f;

    for (int f = 0; f < DMEM; f += 4) {
        const float w0 = W[(f + 0) * DMEM + t];
        const float w1 = W[(f + 1) * DMEM + t];
        const float w2 = W[(f + 2) * DMEM + t];
        const float w3 = W[(f + 3) * DMEM + t];
        #pragma unroll
        for (int i = 0; i < RB; i++) {
            const float4 fv = *(const float4*)&fs[i][f];
            acc[i] = fmaf(fv.x, w0, fmaf(fv.y, w1, fmaf(fv.z, w2, fmaf(fv.w, w3, acc[i]))));
        }
    }

    #pragma unroll
    for (int i = 0; i < RB; i++)
        out[(b0 + i) * DMEM + t] = g_base[(b0 + i) * DMEM + t] + acc[i];
}

// ---------------------------------------------------------------------------
extern "C" void kernel_launch(void* const* d_in, const int* in_sizes, int n_in,
                              void* d_out, int out_size)
{
    const float* nodef  = (const float*)d_in[0];   // node_features  [N,128]
    const float* edgef  = (const float*)d_in[1];   // edge_features  [E,128]
    const float* mem    = (const float*)d_in[2];   // memory         [N,256]
    const float* itab   = (const float*)d_in[3];   // interval_table [300,128]
    const float* bbound = (const float*)d_in[4];   // bin_boundaries [301]
    const float* tw     = (const float*)d_in[5];   // time_w [128]
    const float* tbias  = (const float*)d_in[6];   // time_b [128]
    const float* Wagg   = (const float*)d_in[7];   // W_agg  [256,256]
    const float* ts     = (const float*)d_in[8];   // timestamps [B]
    const float* etimes = (const float*)d_in[9];   // edge_times [B,K]
    const float* ivals  = (const float*)d_in[10];  // intervals [B]
    const float* nivals = (const float*)d_in[11];  // nei_intervals [B,K]
    const int*   srcn   = (const int*)d_in[12];    // source_nodes [B]
    const int*   nbr    = (const int*)d_in[13];    // neighbors [B,K]
    const int*   eidx   = (const int*)d_in[14];    // edge_idxs [B,K]
    float* out = (float*)d_out;

    gather_reduce_kernel<<<BB, 256>>>(nodef, edgef, mem, itab, bbound, tw, tbias,
                                      ts, etimes, ivals, nivals, srcn, nbr, eidx);
    gemm_add_kernel<<<BB / RB, 256>>>(Wagg, out);
}

// round 2
// speedup vs baseline: 1.7409x; 1.7409x over previous
#include <cuda_runtime.h>
#include <math.h>

// Problem constants (fixed by the reference)
#define BB    4096
#define KK    20
#define DN    128
#define DMEM  256
#define DT    128
#define DE    128
#define NBINS 300

// Scratch (no cudaMalloc allowed): base = src0 + nb0_mean, feat = masked mean of cat(ete, ef)
__device__ float g_base[BB * DMEM];
__device__ float g_feat[BB * DMEM];

// ---------------------------------------------------------------------------
// Kernel 1: per-source gather + masked reduction over K neighbors.
// One CTA per source b, 256 threads = one thread per output dim d.
// Warps 0-3: d in [0,128)  -> node_features gather + time-encoding (MUFU cos)
// Warps 4-7: d in [128,256)-> interval-table gather + edge-feature gather
// Branch-free over k: invalid neighbors use safe index 0 and weight 0, so all
// loads are unconditional and ptxas can front-batch them (high MLP).
// ---------------------------------------------------------------------------
__global__ void __launch_bounds__(256) gather_reduce_kernel(
    const float* __restrict__ nodef,   // [N, 128]
    const float* __restrict__ edgef,   // [E, 128]
    const float* __restrict__ mem,     // [N, 256]
    const float* __restrict__ itab,    // [300, 128]
    const float* __restrict__ bbound,  // [301]
    const float* __restrict__ tw,      // [128]
    const float* __restrict__ tbias,   // [128]
    const float* __restrict__ ts,      // [B]
    const float* __restrict__ etimes,  // [B, K]
    const float* __restrict__ ivals,   // [B]
    const float* __restrict__ nivals,  // [B, K]
    const int*   __restrict__ srcn,    // [B]
    const int*   __restrict__ nbr,     // [B, K]
    const int*   __restrict__ eidx)    // [B, K]
{
    const int b = blockIdx.x;
    const int t = threadIdx.x;  // 0..255

    __shared__ float s_bb[NBINS + 1];
    __shared__ int   s_moff[KK];     // safe_n * 256
    __shared__ int   s_noff[KK];     // safe_n * 128
    __shared__ int   s_ioff[KK];     // bin_k * 128
    __shared__ int   s_eoff[KK];     // eidx * 128
    __shared__ float s_vf[KK];       // 1.0 if valid else 0.0
    __shared__ float s_delta[KK];
    __shared__ int   s_sio;          // source interval bin * 128

    for (int i = t; i < NBINS + 1; i += 256) s_bb[i] = bbound[i];
    __syncthreads();

    if (t < KK) {
        int n = nbr[b * KK + t];
        int valid = (n != -1);
        int ns = valid ? n : 0;
        s_vf[t]   = valid ? 1.0f : 0.0f;
        s_moff[t] = ns * DMEM;
        s_noff[t] = ns * DN;
        s_eoff[t] = eidx[b * KK + t] * DE;
        s_delta[t] = ts[b] - etimes[b * KK + t];
        // searchsorted(bbound, x, side='left') - 1, clipped: exact lower_bound
        float x = nivals[b * KK + t];
        int lo = 0, hi = NBINS + 1;
        while (lo < hi) { int mid = (lo + hi) >> 1; if (s_bb[mid] < x) lo = mid + 1; else hi = mid; }
        s_ioff[t] = min(max(lo - 1, 0), NBINS - 1) * DN;
    } else if (t == KK) {
        float x = ivals[b];
        int lo = 0, hi = NBINS + 1;
        while (lo < hi) { int mid = (lo + hi) >> 1; if (s_bb[mid] < x) lo = mid + 1; else hi = mid; }
        s_sio = min(max(lo - 1, 0), NBINS - 1) * DN;
    }
    __syncthreads();

    float cnt = 0.f;
    #pragma unroll
    for (int k = 0; k < KK; k++) cnt += s_vf[k];
    const float inv = 1.0f / fmaxf(cnt, 1.0f);

    const int s = srcn[b];
    float srcv = mem[(size_t)s * DMEM + t];
    float nbsum = 0.f, fsum = 0.f;

    if (t < DN) {
        srcv += nodef[(size_t)s * DN + t];
        const float w_  = tw[t];
        const float bi_ = tbias[t];
        #pragma unroll
        for (int k = 0; k < KK; k++) {
            const float vf = s_vf[k];
            float v = mem[s_moff[k] + t] + nodef[s_noff[k] + t];
            nbsum = fmaf(vf, v, nbsum);
            fsum  = fmaf(vf, __cosf(fmaf(s_delta[k], w_, bi_)), fsum);
        }
    } else {
        const int t2 = t - DN;
        srcv += itab[s_sio + t2];
        #pragma unroll
        for (int k = 0; k < KK; k++) {
            const float vf = s_vf[k];
            float v = mem[s_moff[k] + t] + itab[s_ioff[k] + t2];
            nbsum = fmaf(vf, v, nbsum);
            fsum  = fmaf(vf, edgef[(size_t)s_eoff[k] + t2], fsum);
        }
    }

    g_base[b * DMEM + t] = srcv + nbsum * inv;
    g_feat[b * DMEM + t] = fsum * inv;     // fold /cnt into feat so GEMM output adds directly
}

// ---------------------------------------------------------------------------
// Kernel 2: out[b][d] = base[b][d] + sum_f feat[b][f] * W[f][d]
// Tile: 32 b-rows x 64 d-cols per CTA, grid = 128 b-tiles x 4 d-tiles = 512.
// Thread (ty = t/64, tx = t%64): column d0+tx, 8 accumulator rows.
// feat tile in smem, read as broadcast float4; W streamed (coalesced, L1-reused
// 4x across the ty groups).
// ---------------------------------------------------------------------------
#define TB 32
#define TD 64
__global__ void __launch_bounds__(256) gemm_add_kernel(
    const float* __restrict__ W,   // [256, 256] row-major (f-major)
    float*       __restrict__ out) // [B, 256]
{
    const int t  = threadIdx.x;
    const int tx = t & 63;
    const int ty = t >> 6;                 // 0..3
    const int b0 = (blockIdx.x >> 2) * TB;
    const int d0 = (blockIdx.x & 3) * TD;

    __shared__ float fs[TB][DMEM];  // 32 KB
    #pragma unroll
    for (int i = 0; i < TB; i++) fs[i][t] = g_feat[(b0 + i) * DMEM + t];
    __syncthreads();

    float acc[8];
    #pragma unroll
    for (int i = 0; i < 8; i++) acc[i] = 0.f;

    const int r0 = ty * 8;
    const float* Wp = W + d0 + tx;

    #pragma unroll 4
    for (int f = 0; f < DMEM; f += 4) {
        const float w0 = Wp[(f + 0) * DMEM];
        const float w1 = Wp[(f + 1) * DMEM];
        const float w2 = Wp[(f + 2) * DMEM];
        const float w3 = Wp[(f + 3) * DMEM];
        #pragma unroll
        for (int i = 0; i < 8; i++) {
            const float4 fv = *(const float4*)&fs[r0 + i][f];
            acc[i] = fmaf(fv.x, w0, fmaf(fv.y, w1, fmaf(fv.z, w2, fmaf(fv.w, w3, acc[i]))));
        }
    }

    #pragma unroll
    for (int i = 0; i < 8; i++) {
        const int row = b0 + r0 + i;
        out[row * DMEM + d0 + tx] = g_base[row * DMEM + d0 + tx] + acc[i];
    }
}

// ---------------------------------------------------------------------------
extern "C" void kernel_launch(void* const* d_in, const int* in_sizes, int n_in,
                              void* d_out, int out_size)
{
    const float* nodef  = (const float*)d_in[0];   // node_features  [N,128]
    const float* edgef  = (const float*)d_in[1];   // edge_features  [E,128]
    const float* mem    = (const float*)d_in[2];   // memory         [N,256]
    const float* itab   = (const float*)d_in[3];   // interval_table [300,128]
    const float* bbound = (const float*)d_in[4];   // bin_boundaries [301]
    const float* tw     = (const float*)d_in[5];   // time_w [128]
    const float* tbias  = (const float*)d_in[6];   // time_b [128]
    const float* Wagg   = (const float*)d_in[7];   // W_agg  [256,256]
    const float* ts     = (const float*)d_in[8];   // timestamps [B]
    const float* etimes = (const float*)d_in[9];   // edge_times [B,K]
    const float* ivals  = (const float*)d_in[10];  // intervals [B]
    const float* nivals = (const float*)d_in[11];  // nei_intervals [B,K]
    const int*   srcn   = (const int*)d_in[12];    // source_nodes [B]
    const int*   nbr    = (const int*)d_in[13];    // neighbors [B,K]
    const int*   eidx   = (const int*)d_in[14];    // edge_idxs [B,K]
    float* out = (float*)d_out;

    gather_reduce_kernel<<<BB, 256>>>(nodef, edgef, mem, itab, bbound, tw, tbias,
                                      ts, etimes, ivals, nivals, srcn, nbr, eidx);
    gemm_add_kernel<<<(BB / TB) * (DMEM / TD), 256>>>(Wagg, out);
}

// round 3
// speedup vs baseline: 2.3609x; 1.3562x over previous
#include <cuda_runtime.h>
#include <math.h>

// Problem constants (fixed by the reference)
#define BB    4096
#define KK    20
#define DN    128
#define DMEM  256
#define DT    128
#define DE    128
#define NBINS 300

// Scratch (no cudaMalloc allowed)
__device__ float g_base[BB * DMEM];
__device__ float g_feat[BB * DMEM];

__device__ __forceinline__ float4 f4add(float4 a, float4 b) {
    return make_float4(a.x + b.x, a.y + b.y, a.z + b.z, a.w + b.w);
}
__device__ __forceinline__ float4 f4fma(float s, float4 a, float4 acc) {
    return make_float4(fmaf(s, a.x, acc.x), fmaf(s, a.y, acc.y),
                       fmaf(s, a.z, acc.z), fmaf(s, a.w, acc.w));
}
__device__ __forceinline__ float4 f4scale(float4 a, float s) {
    return make_float4(a.x * s, a.y * s, a.z * s, a.w * s);
}

// ---------------------------------------------------------------------------
// Kernel 1: per-source gather + masked reduction over K neighbors.
// One CTA per source b. 256 threads = 4 k-groups x 64 dim-threads.
// Group g handles k in {g, g+4, ..., g+16}; thread j owns dims [4j, 4j+4)
// via float4 loads (per-warp 512B bursts). Cross-group reduction in smem.
// ---------------------------------------------------------------------------
__global__ void __launch_bounds__(256) gather_reduce_kernel(
    const float* __restrict__ nodef,   // [N, 128]
    const float* __restrict__ edgef,   // [E, 128]
    const float* __restrict__ mem,     // [N, 256]
    const float* __restrict__ itab,    // [300, 128]
    const float* __restrict__ bbound,  // [301]
    const float* __restrict__ tw,      // [128]
    const float* __restrict__ tbias,   // [128]
    const float* __restrict__ ts,      // [B]
    const float* __restrict__ etimes,  // [B, K]
    const float* __restrict__ ivals,   // [B]
    const float* __restrict__ nivals,  // [B, K]
    const int*   __restrict__ srcn,    // [B]
    const int*   __restrict__ nbr,     // [B, K]
    const int*   __restrict__ eidx)    // [B, K]
{
    const int b = blockIdx.x;
    const int t = threadIdx.x;          // 0..255
    const int g = t >> 6;               // k-group 0..3
    const int j = t & 63;               // float4 dim index 0..63

    __shared__ float  s_bb[NBINS + 1];
    __shared__ int    s_m4[KK];         // safe_n * 64  (float4 idx into mem)
    __shared__ int    s_n4[KK];         // safe_n * 32  (float4 idx into nodef)
    __shared__ int    s_i4[KK];         // bin * 32     (float4 idx into itab)
    __shared__ int    s_e4[KK];         // eidx * 32    (float4 idx into edgef)
    __shared__ float  s_vf[KK];
    __shared__ float  s_delta[KK];
    __shared__ int    s_sio4;           // source bin * 32
    __shared__ float4 red_nb[4][64];
    __shared__ float4 red_f[4][64];

    for (int i = t; i < NBINS + 1; i += 256) s_bb[i] = bbound[i];
    __syncthreads();

    if (t < KK) {
        int n = nbr[b * KK + t];
        int valid = (n != -1);
        int ns = valid ? n : 0;
        s_vf[t] = valid ? 1.0f : 0.0f;
        s_m4[t] = ns * 64;
        s_n4[t] = ns * 32;
        s_e4[t] = eidx[b * KK + t] * 32;
        s_delta[t] = ts[b] - etimes[b * KK + t];
        float x = nivals[b * KK + t];
        int lo = 0, hi = NBINS + 1;
        while (lo < hi) { int mid = (lo + hi) >> 1; if (s_bb[mid] < x) lo = mid + 1; else hi = mid; }
        s_i4[t] = min(max(lo - 1, 0), NBINS - 1) * 32;
    } else if (t == KK) {
        float x = ivals[b];
        int lo = 0, hi = NBINS + 1;
        while (lo < hi) { int mid = (lo + hi) >> 1; if (s_bb[mid] < x) lo = mid + 1; else hi = mid; }
        s_sio4 = min(max(lo - 1, 0), NBINS - 1) * 32;
    }
    __syncthreads();

    const float4* __restrict__ mem4   = (const float4*)mem;
    const float4* __restrict__ nodef4 = (const float4*)nodef;
    const float4* __restrict__ itab4  = (const float4*)itab;
    const float4* __restrict__ edgef4 = (const float4*)edgef;

    float4 nb = make_float4(0.f, 0.f, 0.f, 0.f);
    float4 fv = make_float4(0.f, 0.f, 0.f, 0.f);

    if (j < 32) {
        // dims [0,128): node_features gather + time encoding
        const float4 w4 = ((const float4*)tw)[j];
        const float4 b4 = ((const float4*)tbias)[j];
        #pragma unroll
        for (int i = 0; i < 5; i++) {
            const int k = g + 4 * i;
            const float vf = s_vf[k];
            float4 m  = mem4[s_m4[k] + j];
            float4 nf = nodef4[s_n4[k] + j];
            nb = f4fma(vf, f4add(m, nf), nb);
            const float d = s_delta[k];
            fv.x += vf * __cosf(fmaf(d, w4.x, b4.x));
            fv.y += vf * __cosf(fmaf(d, w4.y, b4.y));
            fv.z += vf * __cosf(fmaf(d, w4.z, b4.z));
            fv.w += vf * __cosf(fmaf(d, w4.w, b4.w));
        }
    } else {
        // dims [128,256): interval-table gather + edge-feature gather
        const int j2 = j - 32;
        #pragma unroll
        for (int i = 0; i < 5; i++) {
            const int k = g + 4 * i;
            const float vf = s_vf[k];
            float4 m  = mem4[s_m4[k] + j];
            float4 it = itab4[s_i4[k] + j2];
            nb = f4fma(vf, f4add(m, it), nb);
            float4 ef = edgef4[s_e4[k] + j2];
            fv = f4fma(vf, ef, fv);
        }
    }

    red_nb[g][j] = nb;
    red_f[g][j]  = fv;
    __syncthreads();

    if (t < 64) {
        float cnt = 0.f;
        #pragma unroll
        for (int k = 0; k < KK; k++) cnt += s_vf[k];
        const float inv = 1.0f / fmaxf(cnt, 1.0f);

        float4 nbs = f4add(f4add(red_nb[0][t], red_nb[1][t]),
                           f4add(red_nb[2][t], red_nb[3][t]));
        float4 fvs = f4add(f4add(red_f[0][t], red_f[1][t]),
                           f4add(red_f[2][t], red_f[3][t]));

        const int s = srcn[b];
        float4 sv = mem4[(size_t)s * 64 + t];
        if (t < 32) sv = f4add(sv, nodef4[(size_t)s * 32 + t]);
        else        sv = f4add(sv, itab4[s_sio4 + (t - 32)]);

        ((float4*)g_base)[b * 64 + t] = f4add(sv, f4scale(nbs, inv));
        ((float4*)g_feat)[b * 64 + t] = f4scale(fvs, inv);
    }
}

// ---------------------------------------------------------------------------
// Kernel 2: out[b][d] = base[b][d] + sum_f feat[b][f] * W[f][d]
// Tile: 32 b-rows x 64 d-cols. Both W-tile (64KB) and feat-tile (32KB) staged
// in dynamic shared memory so the inner loop is pure LDS + FFMA (no L2
// latency on the critical path). 96KB smem -> 2 CTAs/SM, 16 warps.
// ---------------------------------------------------------------------------
#define TB 32
#define TD 64
__global__ void __launch_bounds__(256) gemm_add_kernel(
    const float* __restrict__ W,   // [256, 256] row-major (f-major)
    float*       __restrict__ out) // [B, 256]
{
    extern __shared__ float sm[];
    float* Ws = sm;                 // [256][64]
    float* fs = sm + DMEM * TD;     // [32][256]

    const int t  = threadIdx.x;
    const int b0 = (blockIdx.x >> 2) * TB;
    const int d0 = (blockIdx.x & 3) * TD;

    // Load W tile: 4096 float4, 16 per thread. Ws[f][c] = W[f*256 + d0 + c]
    {
        const float4* W4 = (const float4*)(W + d0);
        float4* Ws4 = (float4*)Ws;
        #pragma unroll
        for (int r = 0; r < 16; r++) {
            int i = r * 256 + t;            // float4 index: f = i>>4, c4 = i&15
            int f = i >> 4, c4 = i & 15;
            Ws4[i] = W4[f * 64 + c4];       // W row stride = 256 floats = 64 float4
        }
    }
    // Load feat tile: 2048 float4, 8 per thread (rows contiguous)
    {
        const float4* F4 = ((const float4*)g_feat) + b0 * 64;
        float4* fs4 = (float4*)fs;
        #pragma unroll
        for (int r = 0; r < 8; r++) fs4[r * 256 + t] = F4[r * 256 + t];
    }
    __syncthreads();

    const int tx = t & 63;
    const int ty = t >> 6;
    const int r0 = ty * 8;

    float acc[8];
    #pragma unroll
    for (int i = 0; i < 8; i++) acc[i] = 0.f;

    #pragma unroll 4
    for (int f = 0; f < DMEM; f += 4) {
        const float w0 = Ws[(f + 0) * TD + tx];
        const float w1 = Ws[(f + 1) * TD + tx];
        const float w2 = Ws[(f + 2) * TD + tx];
        const float w3 = Ws[(f + 3) * TD + tx];
        #pragma unroll
        for (int i = 0; i < 8; i++) {
            const float4 fvv = *(const float4*)&fs[(r0 + i) * DMEM + f];
            acc[i] = fmaf(fvv.x, w0, fmaf(fvv.y, w1, fmaf(fvv.z, w2, fmaf(fvv.w, w3, acc[i]))));
        }
    }

    #pragma unroll
    for (int i = 0; i < 8; i++) {
        const int row = b0 + r0 + i;
        out[row * DMEM + d0 + tx] = g_base[row * DMEM + d0 + tx] + acc[i];
    }
}

// ---------------------------------------------------------------------------
extern "C" void kernel_launch(void* const* d_in, const int* in_sizes, int n_in,
                              void* d_out, int out_size)
{
    const float* nodef  = (const float*)d_in[0];
    const float* edgef  = (const float*)d_in[1];
    const float* mem    = (const float*)d_in[2];
    const float* itab   = (const float*)d_in[3];
    const float* bbound = (const float*)d_in[4];
    const float* tw     = (const float*)d_in[5];
    const float* tbias  = (const float*)d_in[6];
    const float* Wagg   = (const float*)d_in[7];
    const float* ts     = (const float*)d_in[8];
    const float* etimes = (const float*)d_in[9];
    const float* ivals  = (const float*)d_in[10];
    const float* nivals = (const float*)d_in[11];
    const int*   srcn   = (const int*)d_in[12];
    const int*   nbr    = (const int*)d_in[13];
    const int*   eidx   = (const int*)d_in[14];
    float* out = (float*)d_out;

    const int smem2 = (DMEM * TD + TB * DMEM) * (int)sizeof(float);  // 96 KB
    cudaFuncSetAttribute(gemm_add_kernel,
                         cudaFuncAttributeMaxDynamicSharedMemorySize, smem2);

    gather_reduce_kernel<<<BB, 256>>>(nodef, edgef, mem, itab, bbound, tw, tbias,
                                      ts, etimes, ivals, nivals, srcn, nbr, eidx);
    gemm_add_kernel<<<(BB / TB) * (DMEM / TD), 256, smem2>>>(Wagg, out);
}

// round 5
// speedup vs baseline: 2.9122x; 1.2335x over previous
#include <cuda_runtime.h>
#include <math.h>
#include <stdint.h>

// Problem constants (fixed by the reference)
#define BB    4096
#define KK    20
#define DN    128
#define DMEM  256
#define DT    128
#define DE    128
#define NBINS 300

// Scratch (no cudaMalloc allowed)
__device__ float g_base[BB * DMEM];
__device__ float g_feat[BB * DMEM];
__device__ uint32_t g_Wp[DMEM * DMEM];   // W packed in B-fragment order (tf32 bits)
__device__ uint32_t g_Ap[BB * DMEM];     // feat packed in A-fragment order (tf32 bits)

__device__ __forceinline__ float4 f4add(float4 a, float4 b) {
    return make_float4(a.x + b.x, a.y + b.y, a.z + b.z, a.w + b.w);
}
__device__ __forceinline__ float4 f4fma(float s, float4 a, float4 acc) {
    return make_float4(fmaf(s, a.x, acc.x), fmaf(s, a.y, acc.y),
                       fmaf(s, a.z, acc.z), fmaf(s, a.w, acc.w));
}
__device__ __forceinline__ float4 f4scale(float4 a, float s) {
    return make_float4(a.x * s, a.y * s, a.z * s, a.w * s);
}
__device__ __forceinline__ uint32_t to_tf32(float x) {
    uint32_t r;
    asm("cvt.rn.tf32.f32 %0, %1;" : "=r"(r) : "f"(x));
    return r;
}
__device__ __forceinline__ void mma_tf32(float c[4], const uint32_t a[4],
                                         const uint32_t b0, const uint32_t b1) {
    asm volatile(
        "mma.sync.aligned.m16n8k8.row.col.f32.tf32.tf32.f32 "
        "{%0,%1,%2,%3}, {%4,%5,%6,%7}, {%8,%9}, {%0,%1,%2,%3};"
        : "+f"(c[0]), "+f"(c[1]), "+f"(c[2]), "+f"(c[3])
        : "r"(a[0]), "r"(a[1]), "r"(a[2]), "r"(a[3]), "r"(b0), "r"(b1));
}

// ---------------------------------------------------------------------------
// Pack W -> g_Wp in B-fragment order (tf32).
// Layout: ((nt*32 + kstep)*8 + nf)*64 + lane*2 + p
//   value = W[k][n], k = kstep*8 + (lane&3) + p*4, n = nt*64 + nf*8 + (lane>>2)
// ---------------------------------------------------------------------------
__global__ void __launch_bounds__(256) pack_w_kernel(const float* __restrict__ W)
{
    int idx = blockIdx.x * 1024 + threadIdx.x * 4;  // 64 CTAs cover 65536
    #pragma unroll
    for (int e = 0; e < 4; e++) {
        int i = idx + e;
        int p     = i & 1;
        int lane  = (i >> 1) & 31;
        int nf    = (i >> 6) & 7;
        int kstep = (i >> 9) & 31;
        int nt    = i >> 14;
        int k = kstep * 8 + (lane & 3) + p * 4;
        int n = nt * 64 + nf * 8 + (lane >> 2);
        g_Wp[i] = to_tf32(W[k * DMEM + n]);
    }
}

// ---------------------------------------------------------------------------
// Pack g_feat -> g_Ap in A-fragment order (tf32).
// Layout: ((rt*32 + kstep)*2 + mf)*128 + lane*4 + reg
//   b = rt*32 + mf*16 + (lane>>2) + (reg&1)*8
//   f = kstep*8 + (lane&3) + (reg>>1)*4
// ---------------------------------------------------------------------------
__global__ void __launch_bounds__(256) pack_a_kernel()
{
    int base = blockIdx.x * 1024 + threadIdx.x * 4;  // 1024 CTAs cover 1M
    uint32_t v[4];
    #pragma unroll
    for (int reg = 0; reg < 4; reg++) {
        int i = base + reg;
        int lane  = (i >> 2) & 31;
        int mf    = (i >> 7) & 1;
        int kstep = (i >> 8) & 31;
        int rt    = i >> 13;
        int b = rt * 32 + mf * 16 + (lane >> 2) + (reg & 1) * 8;
        int f = kstep * 8 + (lane & 3) + (reg >> 1) * 4;
        v[reg] = to_tf32(g_feat[b * DMEM + f]);
    }
    *(uint4*)&g_Ap[base] = make_uint4(v[0], v[1], v[2], v[3]);
}

// ---------------------------------------------------------------------------
// Kernel 1: per-source gather + masked reduction over K neighbors.
// (unchanged from R3 — ~37 us, near its DRAM-gather floor)
// ---------------------------------------------------------------------------
__global__ void __launch_bounds__(256) gather_reduce_kernel(
    const float* __restrict__ nodef,   // [N, 128]
    const float* __restrict__ edgef,   // [E, 128]
    const float* __restrict__ mem,     // [N, 256]
    const float* __restrict__ itab,    // [300, 128]
    const float* __restrict__ bbound,  // [301]
    const float* __restrict__ tw,      // [128]
    const float* __restrict__ tbias,   // [128]
    const float* __restrict__ ts,      // [B]
    const float* __restrict__ etimes,  // [B, K]
    const float* __restrict__ ivals,   // [B]
    const float* __restrict__ nivals,  // [B, K]
    const int*   __restrict__ srcn,    // [B]
    const int*   __restrict__ nbr,     // [B, K]
    const int*   __restrict__ eidx)    // [B, K]
{
    const int b = blockIdx.x;
    const int t = threadIdx.x;          // 0..255
    const int g = t >> 6;               // k-group 0..3
    const int j = t & 63;               // float4 dim index 0..63

    __shared__ float  s_bb[NBINS + 1];
    __shared__ int    s_m4[KK];
    __shared__ int    s_n4[KK];
    __shared__ int    s_i4[KK];
    __shared__ int    s_e4[KK];
    __shared__ float  s_vf[KK];
    __shared__ float  s_delta[KK];
    __shared__ int    s_sio4;
    __shared__ float4 red_nb[4][64];
    __shared__ float4 red_f[4][64];

    for (int i = t; i < NBINS + 1; i += 256) s_bb[i] = bbound[i];
    __syncthreads();

    if (t < KK) {
        int n = nbr[b * KK + t];
        int valid = (n != -1);
        int ns = valid ? n : 0;
        s_vf[t] = valid ? 1.0f : 0.0f;
        s_m4[t] = ns * 64;
        s_n4[t] = ns * 32;
        s_e4[t] = eidx[b * KK + t] * 32;
        s_delta[t] = ts[b] - etimes[b * KK + t];
        float x = nivals[b * KK + t];
        int lo = 0, hi = NBINS + 1;
        while (lo < hi) { int mid = (lo + hi) >> 1; if (s_bb[mid] < x) lo = mid + 1; else hi = mid; }
        s_i4[t] = min(max(lo - 1, 0), NBINS - 1) * 32;
    } else if (t == KK) {
        float x = ivals[b];
        int lo = 0, hi = NBINS + 1;
        while (lo < hi) { int mid = (lo + hi) >> 1; if (s_bb[mid] < x) lo = mid + 1; else hi = mid; }
        s_sio4 = min(max(lo - 1, 0), NBINS - 1) * 32;
    }
    __syncthreads();

    const float4* __restrict__ mem4   = (const float4*)mem;
    const float4* __restrict__ nodef4 = (const float4*)nodef;
    const float4* __restrict__ itab4  = (const float4*)itab;
    const float4* __restrict__ edgef4 = (const float4*)edgef;

    float4 nb = make_float4(0.f, 0.f, 0.f, 0.f);
    float4 fv = make_float4(0.f, 0.f, 0.f, 0.f);

    if (j < 32) {
        const float4 w4 = ((const float4*)tw)[j];
        const float4 b4 = ((const float4*)tbias)[j];
        #pragma unroll
        for (int i = 0; i < 5; i++) {
            const int k = g + 4 * i;
            const float vf = s_vf[k];
            float4 m  = mem4[s_m4[k] + j];
            float4 nf = nodef4[s_n4[k] + j];
            nb = f4fma(vf, f4add(m, nf), nb);
            const float d = s_delta[k];
            fv.x += vf * __cosf(fmaf(d, w4.x, b4.x));
            fv.y += vf * __cosf(fmaf(d, w4.y, b4.y));
            fv.z += vf * __cosf(fmaf(d, w4.z, b4.z));
            fv.w += vf * __cosf(fmaf(d, w4.w, b4.w));
        }
    } else {
        const int j2 = j - 32;
        #pragma unroll
        for (int i = 0; i < 5; i++) {
            const int k = g + 4 * i;
            const float vf = s_vf[k];
            float4 m  = mem4[s_m4[k] + j];
            float4 it = itab4[s_i4[k] + j2];
            nb = f4fma(vf, f4add(m, it), nb);
            float4 ef = edgef4[s_e4[k] + j2];
            fv = f4fma(vf, ef, fv);
        }
    }

    red_nb[g][j] = nb;
    red_f[g][j]  = fv;
    __syncthreads();

    if (t < 64) {
        float cnt = 0.f;
        #pragma unroll
        for (int k = 0; k < KK; k++) cnt += s_vf[k];
        const float inv = 1.0f / fmaxf(cnt, 1.0f);

        float4 nbs = f4add(f4add(red_nb[0][t], red_nb[1][t]),
                           f4add(red_nb[2][t], red_nb[3][t]));
        float4 fvs = f4add(f4add(red_f[0][t], red_f[1][t]),
                           f4add(red_f[2][t], red_f[3][t]));

        const int s = srcn[b];
        float4 sv = mem4[(size_t)s * 64 + t];
        if (t < 32) sv = f4add(sv, nodef4[(size_t)s * 32 + t]);
        else        sv = f4add(sv, itab4[s_sio4 + (t - 32)]);

        ((float4*)g_base)[b * 64 + t] = f4add(sv, f4scale(nbs, inv));
        ((float4*)g_feat)[b * 64 + t] = f4scale(fvs, inv);
    }
}

// ---------------------------------------------------------------------------
// Kernel 2: tf32 mma.sync GEMM.  out = base + feat @ W
// CTA tile: M=128 (b) x N=64 (d), K=256. Grid = 32 x 4 = 128 CTAs.
// 8 warps = 4 (M, 32 rows each) x 2 (N, 32 cols each).
// B (W n-tile) staged in 64KB smem in fragment order -> LDS.64 conflict-free.
// A frags loaded straight from g_Ap with LDG.128 (prepacked, no smem).
// ---------------------------------------------------------------------------
__global__ void __launch_bounds__(256) mma_kernel(float* __restrict__ out)
{
    extern __shared__ uint32_t Bs[];   // 16384 u32 = 64KB: [kstep][nf][lane][2]
    const int tid  = threadIdx.x;
    const int lane = tid & 31;
    const int wid  = tid >> 5;
    const int bt   = blockIdx.x >> 2;      // 0..31  (128 rows each)
    const int nt   = blockIdx.x & 3;       // 0..3   (64 cols each)
    const int wm   = wid & 3;              // warp m sub-tile (32 rows)
    const int wn   = wid >> 2;             // warp n half (32 cols)
    const int rt   = bt * 4 + wm;          // 32-row tile index into g_Ap

    // Stage B tile (fragment-ordered): 4096 uint4, 16 per thread, coalesced.
    {
        const uint4* src = (const uint4*)&g_Wp[nt * 16384];
        uint4* dst = (uint4*)Bs;
        #pragma unroll
        for (int i = 0; i < 16; i++) dst[i * 256 + tid] = src[i * 256 + tid];
    }
    __syncthreads();

    float acc[2][4][4];
    #pragma unroll
    for (int mf = 0; mf < 2; mf++)
        #pragma unroll
        for (int j = 0; j < 4; j++)
            #pragma unroll
            for (int q = 0; q < 4; q++) acc[mf][j][q] = 0.f;

    const uint4* Ap4 = (const uint4*)g_Ap;   // frag = uint4 at ((rt*32+k)*2+mf)*32 + lane

    #pragma unroll 4
    for (int ks = 0; ks < 32; ks++) {
        uint4 A0 = Ap4[((rt * 32 + ks) * 2 + 0) * 32 + lane];
        uint4 A1 = Ap4[((rt * 32 + ks) * 2 + 1) * 32 + lane];
        uint32_t a0[4] = {A0.x, A0.y, A0.z, A0.w};
        uint32_t a1[4] = {A1.x, A1.y, A1.z, A1.w};
        #pragma unroll
        for (int j = 0; j < 4; j++) {
            const uint32_t* bp = &Bs[((ks * 8) + wn * 4 + j) * 64 + lane * 2];
            uint32_t b0 = bp[0], b1 = bp[1];
            mma_tf32(acc[0][j], a0, b0, b1);
            mma_tf32(acc[1][j], a1, b0, b1);
        }
    }

    // Epilogue: C layout c0=C[g][2t], c1=C[g][2t+1], c2=C[g+8][2t], c3=C[g+8][2t+1]
    const int g  = lane >> 2;
    const int tg = lane & 3;
    const int m0 = bt * 128 + wm * 32;
    const int c0 = nt * 64 + wn * 32 + tg * 2;
    #pragma unroll
    for (int mf = 0; mf < 2; mf++) {
        const int r0 = m0 + mf * 16 + g;
        #pragma unroll
        for (int j = 0; j < 4; j++) {
            const int c = c0 + j * 8;
            float2 ba = *(const float2*)&g_base[r0 * DMEM + c];
            float2 bb = *(const float2*)&g_base[(r0 + 8) * DMEM + c];
            float2 oa = make_float2(ba.x + acc[mf][j][0], ba.y + acc[mf][j][1]);
            float2 ob = make_float2(bb.x + acc[mf][j][2], bb.y + acc[mf][j][3]);
            *(float2*)&out[r0 * DMEM + c]       = oa;
            *(float2*)&out[(r0 + 8) * DMEM + c] = ob;
        }
    }
}

// ---------------------------------------------------------------------------
extern "C" void kernel_launch(void* const* d_in, const int* in_sizes, int n_in,
                              void* d_out, int out_size)
{
    const float* nodef  = (const float*)d_in[0];
    const float* edgef  = (const float*)d_in[1];
    const float* mem    = (const float*)d_in[2];
    const float* itab   = (const float*)d_in[3];
    const float* bbound = (const float*)d_in[4];
    const float* tw     = (const float*)d_in[5];
    const float* tbias  = (const float*)d_in[6];
    const float* Wagg   = (const float*)d_in[7];
    const float* ts     = (const float*)d_in[8];
    const float* etimes = (const float*)d_in[9];
    const float* ivals  = (const float*)d_in[10];
    const float* nivals = (const float*)d_in[11];
    const int*   srcn   = (const int*)d_in[12];
    const int*   nbr    = (const int*)d_in[13];
    const int*   eidx   = (const int*)d_in[14];
    float* out = (float*)d_out;

    cudaFuncSetAttribute(mma_kernel,
                         cudaFuncAttributeMaxDynamicSharedMemorySize, 65536);

    pack_w_kernel<<<64, 256>>>(Wagg);
    gather_reduce_kernel<<<BB, 256>>>(nodef, edgef, mem, itab, bbound, tw, tbias,
                                      ts, etimes, ivals, nivals, srcn, nbr, eidx);
    pack_a_kernel<<<1024, 256>>>();
    mma_kernel<<<128, 256, 65536>>>(out);
}

// round 6
// speedup vs baseline: 3.0165x; 1.0358x over previous
#include <cuda_runtime.h>
#include <math.h>
#include <stdint.h>

// Problem constants (fixed by the reference)
#define BB    4096
#define KK    20
#define DN    128
#define DMEM  256
#define DT    128
#define DE    128
#define NBINS 300

// Scratch (no cudaMalloc allowed)
__device__ float g_base[BB * DMEM];
__device__ float g_feat[BB * DMEM];
__device__ uint32_t g_Wp[DMEM * DMEM];   // W packed in B-fragment order (tf32 bits)
__device__ uint32_t g_Ap[BB * DMEM];     // feat packed in A-fragment order (tf32 bits)

__device__ __forceinline__ float4 f4add(float4 a, float4 b) {
    return make_float4(a.x + b.x, a.y + b.y, a.z + b.z, a.w + b.w);
}
__device__ __forceinline__ float4 f4fma(float s, float4 a, float4 acc) {
    return make_float4(fmaf(s, a.x, acc.x), fmaf(s, a.y, acc.y),
                       fmaf(s, a.z, acc.z), fmaf(s, a.w, acc.w));
}
__device__ __forceinline__ float4 f4scale(float4 a, float s) {
    return make_float4(a.x * s, a.y * s, a.z * s, a.w * s);
}
__device__ __forceinline__ uint32_t to_tf32(float x) {
    uint32_t r;
    asm("cvt.rn.tf32.f32 %0, %1;" : "=r"(r) : "f"(x));
    return r;
}
__device__ __forceinline__ void mma_tf32(float c[4], const uint32_t a[4],
                                         const uint32_t b0, const uint32_t b1) {
    asm volatile(
        "mma.sync.aligned.m16n8k8.row.col.f32.tf32.tf32.f32 "
        "{%0,%1,%2,%3}, {%4,%5,%6,%7}, {%8,%9}, {%0,%1,%2,%3};"
        : "+f"(c[0]), "+f"(c[1]), "+f"(c[2]), "+f"(c[3])
        : "r"(a[0]), "r"(a[1]), "r"(a[2]), "r"(a[3]), "r"(b0), "r"(b1));
}

// ---------------------------------------------------------------------------
// Pack W -> g_Wp in B-fragment order (tf32).
// Layout: ((nt*32 + kstep)*8 + nf)*64 + lane*2 + p
//   value = W[k][n], k = kstep*8 + (lane&3) + p*4, n = nt*64 + nf*8 + (lane>>2)
// ---------------------------------------------------------------------------
__global__ void __launch_bounds__(256) pack_w_kernel(const float* __restrict__ W)
{
    int idx = blockIdx.x * 1024 + threadIdx.x * 4;  // 64 CTAs cover 65536
    #pragma unroll
    for (int e = 0; e < 4; e++) {
        int i = idx + e;
        int p     = i & 1;
        int lane  = (i >> 1) & 31;
        int nf    = (i >> 6) & 7;
        int kstep = (i >> 9) & 31;
        int nt    = i >> 14;
        int k = kstep * 8 + (lane & 3) + p * 4;
        int n = nt * 64 + nf * 8 + (lane >> 2);
        g_Wp[i] = to_tf32(W[k * DMEM + n]);
    }
}

// ---------------------------------------------------------------------------
// Pack g_feat -> g_Ap in A-fragment order (tf32).
// Layout: ((rt*32 + kstep)*2 + mf)*128 + lane*4 + reg
//   b = rt*32 + mf*16 + (lane>>2) + (reg&1)*8
//   f = kstep*8 + (lane&3) + (reg>>1)*4
// ---------------------------------------------------------------------------
__global__ void __launch_bounds__(256) pack_a_kernel()
{
    int base = blockIdx.x * 1024 + threadIdx.x * 4;  // 1024 CTAs cover 1M
    uint32_t v[4];
    #pragma unroll
    for (int reg = 0; reg < 4; reg++) {
        int i = base + reg;
        int lane  = (i >> 2) & 31;
        int mf    = (i >> 7) & 1;
        int kstep = (i >> 8) & 31;
        int rt    = i >> 13;
        int b = rt * 32 + mf * 16 + (lane >> 2) + (reg & 1) * 8;
        int f = kstep * 8 + (lane & 3) + (reg >> 1) * 4;
        v[reg] = to_tf32(g_feat[b * DMEM + f]);
    }
    *(uint4*)&g_Ap[base] = make_uint4(v[0], v[1], v[2], v[3]);
}

// ---------------------------------------------------------------------------
// Kernel 1: per-source gather + masked reduction over K neighbors.
// (unchanged — ~36 us, near its DRAM-gather floor)
// ---------------------------------------------------------------------------
__global__ void __launch_bounds__(256) gather_reduce_kernel(
    const float* __restrict__ nodef,   // [N, 128]
    const float* __restrict__ edgef,   // [E, 128]
    const float* __restrict__ mem,     // [N, 256]
    const float* __restrict__ itab,    // [300, 128]
    const float* __restrict__ bbound,  // [301]
    const float* __restrict__ tw,      // [128]
    const float* __restrict__ tbias,   // [128]
    const float* __restrict__ ts,      // [B]
    const float* __restrict__ etimes,  // [B, K]
    const float* __restrict__ ivals,   // [B]
    const float* __restrict__ nivals,  // [B, K]
    const int*   __restrict__ srcn,    // [B]
    const int*   __restrict__ nbr,     // [B, K]
    const int*   __restrict__ eidx)    // [B, K]
{
    const int b = blockIdx.x;
    const int t = threadIdx.x;          // 0..255
    const int g = t >> 6;               // k-group 0..3
    const int j = t & 63;               // float4 dim index 0..63

    __shared__ float  s_bb[NBINS + 1];
    __shared__ int    s_m4[KK];
    __shared__ int    s_n4[KK];
    __shared__ int    s_i4[KK];
    __shared__ int    s_e4[KK];
    __shared__ float  s_vf[KK];
    __shared__ float  s_delta[KK];
    __shared__ int    s_sio4;
    __shared__ float4 red_nb[4][64];
    __shared__ float4 red_f[4][64];

    for (int i = t; i < NBINS + 1; i += 256) s_bb[i] = bbound[i];
    __syncthreads();

    if (t < KK) {
        int n = nbr[b * KK + t];
        int valid = (n != -1);
        int ns = valid ? n : 0;
        s_vf[t] = valid ? 1.0f : 0.0f;
        s_m4[t] = ns * 64;
        s_n4[t] = ns * 32;
        s_e4[t] = eidx[b * KK + t] * 32;
        s_delta[t] = ts[b] - etimes[b * KK + t];
        float x = nivals[b * KK + t];
        int lo = 0, hi = NBINS + 1;
        while (lo < hi) { int mid = (lo + hi) >> 1; if (s_bb[mid] < x) lo = mid + 1; else hi = mid; }
        s_i4[t] = min(max(lo - 1, 0), NBINS - 1) * 32;
    } else if (t == KK) {
        float x = ivals[b];
        int lo = 0, hi = NBINS + 1;
        while (lo < hi) { int mid = (lo + hi) >> 1; if (s_bb[mid] < x) lo = mid + 1; else hi = mid; }
        s_sio4 = min(max(lo - 1, 0), NBINS - 1) * 32;
    }
    __syncthreads();

    const float4* __restrict__ mem4   = (const float4*)mem;
    const float4* __restrict__ nodef4 = (const float4*)nodef;
    const float4* __restrict__ itab4  = (const float4*)itab;
    const float4* __restrict__ edgef4 = (const float4*)edgef;

    float4 nb = make_float4(0.f, 0.f, 0.f, 0.f);
    float4 fv = make_float4(0.f, 0.f, 0.f, 0.f);

    if (j < 32) {
        const float4 w4 = ((const float4*)tw)[j];
        const float4 b4 = ((const float4*)tbias)[j];
        #pragma unroll
        for (int i = 0; i < 5; i++) {
            const int k = g + 4 * i;
            const float vf = s_vf[k];
            float4 m  = mem4[s_m4[k] + j];
            float4 nf = nodef4[s_n4[k] + j];
            nb = f4fma(vf, f4add(m, nf), nb);
            const float d = s_delta[k];
            fv.x += vf * __cosf(fmaf(d, w4.x, b4.x));
            fv.y += vf * __cosf(fmaf(d, w4.y, b4.y));
            fv.z += vf * __cosf(fmaf(d, w4.z, b4.z));
            fv.w += vf * __cosf(fmaf(d, w4.w, b4.w));
        }
    } else {
        const int j2 = j - 32;
        #pragma unroll
        for (int i = 0; i < 5; i++) {
            const int k = g + 4 * i;
            const float vf = s_vf[k];
            float4 m  = mem4[s_m4[k] + j];
            float4 it = itab4[s_i4[k] + j2];
            nb = f4fma(vf, f4add(m, it), nb);
            float4 ef = edgef4[s_e4[k] + j2];
            fv = f4fma(vf, ef, fv);
        }
    }

    red_nb[g][j] = nb;
    red_f[g][j]  = fv;
    __syncthreads();

    if (t < 64) {
        float cnt = 0.f;
        #pragma unroll
        for (int k = 0; k < KK; k++) cnt += s_vf[k];
        const float inv = 1.0f / fmaxf(cnt, 1.0f);

        float4 nbs = f4add(f4add(red_nb[0][t], red_nb[1][t]),
                           f4add(red_nb[2][t], red_nb[3][t]));
        float4 fvs = f4add(f4add(red_f[0][t], red_f[1][t]),
                           f4add(red_f[2][t], red_f[3][t]));

        const int s = srcn[b];
        float4 sv = mem4[(size_t)s * 64 + t];
        if (t < 32) sv = f4add(sv, nodef4[(size_t)s * 32 + t]);
        else        sv = f4add(sv, itab4[s_sio4 + (t - 32)]);

        ((float4*)g_base)[b * 64 + t] = f4add(sv, f4scale(nbs, inv));
        ((float4*)g_feat)[b * 64 + t] = f4scale(fvs, inv);
    }
}

// ---------------------------------------------------------------------------
// Kernel 2: tf32 mma.sync GEMM.  out = base + feat @ W
// CTA tile: M=64 (b) x N=64 (d), K=256. Grid = 64 x 4 = 256 CTAs
// (>148 SMs, ~2 CTAs/SM via 64KB smem -> 16 warps for latency cover).
// 8 warps = 2 (M, 32 rows) x 4 (N, 16 cols).
// B (W n-tile) staged in 64KB smem in fragment order -> LDS.64 conflict-free.
// A frags loaded from g_Ap with LDG.128, fully unrolled K loop + ping-pong
// prefetch so ptxas front-batches the independent loads (high MLP).
// ---------------------------------------------------------------------------
__global__ void __launch_bounds__(256) mma_kernel(float* __restrict__ out)
{
    extern __shared__ uint32_t Bs[];   // 16384 u32 = 64KB: [kstep][nf][lane][2]
    const int tid  = threadIdx.x;
    const int lane = tid & 31;
    const int wid  = tid >> 5;
    const int bt   = blockIdx.x >> 2;      // 0..63  (64 rows each)
    const int nt   = blockIdx.x & 3;       // 0..3   (64 cols each)
    const int wm   = wid & 1;              // warp m sub-tile (32 rows)
    const int wn   = wid >> 1;             // warp n sub-tile (16 cols)
    const int rt   = bt * 2 + wm;          // 32-row tile index into g_Ap

    // Stage B tile (fragment-ordered): 4096 uint4, 16 per thread, coalesced.
    {
        const uint4* src = (const uint4*)&g_Wp[nt * 16384];
        uint4* dst = (uint4*)Bs;
        #pragma unroll
        for (int i = 0; i < 16; i++) dst[i * 256 + tid] = src[i * 256 + tid];
    }
    __syncthreads();

    float acc[2][2][4];
    #pragma unroll
    for (int mf = 0; mf < 2; mf++)
        #pragma unroll
        for (int j = 0; j < 2; j++)
            #pragma unroll
            for (int q = 0; q < 4; q++) acc[mf][j][q] = 0.f;

    const uint4* Ap4 = (const uint4*)g_Ap;   // frag = uint4 at ((rt*32+ks)*2+mf)*32 + lane
    const uint4* apb = Ap4 + (rt * 32) * 2 * 32 + lane;

    uint4 Ac0 = apb[0];
    uint4 Ac1 = apb[32];

    #pragma unroll
    for (int ks = 0; ks < 32; ks++) {
        uint4 An0, An1;
        if (ks < 31) {
            An0 = apb[(ks + 1) * 64];
            An1 = apb[(ks + 1) * 64 + 32];
        }
        uint32_t a0[4] = {Ac0.x, Ac0.y, Ac0.z, Ac0.w};
        uint32_t a1[4] = {Ac1.x, Ac1.y, Ac1.z, Ac1.w};
        #pragma unroll
        for (int j = 0; j < 2; j++) {
            const uint32_t* bp = &Bs[((ks * 8) + wn * 2 + j) * 64 + lane * 2];
            uint32_t b0 = bp[0], b1 = bp[1];
            mma_tf32(acc[0][j], a0, b0, b1);
            mma_tf32(acc[1][j], a1, b0, b1);
        }
        Ac0 = An0;
        Ac1 = An1;
    }

    // Epilogue: C layout c0=C[g][2t], c1=C[g][2t+1], c2=C[g+8][2t], c3=C[g+8][2t+1]
    const int g  = lane >> 2;
    const int tg = lane & 3;
    const int m0 = bt * 64 + wm * 32;
    const int c0 = nt * 64 + wn * 16 + tg * 2;
    #pragma unroll
    for (int mf = 0; mf < 2; mf++) {
        const int r0 = m0 + mf * 16 + g;
        #pragma unroll
        for (int j = 0; j < 2; j++) {
            const int c = c0 + j * 8;
            float2 ba = *(const float2*)&g_base[r0 * DMEM + c];
            float2 bb = *(const float2*)&g_base[(r0 + 8) * DMEM + c];
            float2 oa = make_float2(ba.x + acc[mf][j][0], ba.y + acc[mf][j][1]);
            float2 ob = make_float2(bb.x + acc[mf][j][2], bb.y + acc[mf][j][3]);
            *(float2*)&out[r0 * DMEM + c]       = oa;
            *(float2*)&out[(r0 + 8) * DMEM + c] = ob;
        }
    }
}

// ---------------------------------------------------------------------------
extern "C" void kernel_launch(void* const* d_in, const int* in_sizes, int n_in,
                              void* d_out, int out_size)
{
    const float* nodef  = (const float*)d_in[0];
    const float* edgef  = (const float*)d_in[1];
    const float* mem    = (const float*)d_in[2];
    const float* itab   = (const float*)d_in[3];
    const float* bbound = (const float*)d_in[4];
    const float* tw     = (const float*)d_in[5];
    const float* tbias  = (const float*)d_in[6];
    const float* Wagg   = (const float*)d_in[7];
    const float* ts     = (const float*)d_in[8];
    const float* etimes = (const float*)d_in[9];
    const float* ivals  = (const float*)d_in[10];
    const float* nivals = (const float*)d_in[11];
    const int*   srcn   = (const int*)d_in[12];
    const int*   nbr    = (const int*)d_in[13];
    const int*   eidx   = (const int*)d_in[14];
    float* out = (float*)d_out;

    cudaFuncSetAttribute(mma_kernel,
                         cudaFuncAttributeMaxDynamicSharedMemorySize, 65536);

    pack_w_kernel<<<64, 256>>>(Wagg);
    gather_reduce_kernel<<<BB, 256>>>(nodef, edgef, mem, itab, bbound, tw, tbias,
                                      ts, etimes, ivals, nivals, srcn, nbr, eidx);
    pack_a_kernel<<<1024, 256>>>();
    mma_kernel<<<256, 256, 65536>>>(out);
}

// round 8
// speedup vs baseline: 3.1250x; 1.0360x over previous
#include <cuda_runtime.h>
#include <math.h>
#include <stdint.h>

// Problem constants (fixed by the reference)
#define BB    4096
#define KK    20
#define DMEM  256
#define NBINS 300
#define ROWS  16            // rows per CTA
#define NCTA  (BB / ROWS)   // 256
#define FSTR  260           // smem row stride in floats (pad: 4g+tg banks distinct)

// Scratch (no cudaMalloc allowed): only packed W survives between kernels.
__device__ uint32_t g_Wp[DMEM * DMEM];  // tf32 bits, B-fragment order per warp-tile

__device__ __forceinline__ float4 f4add(float4 a, float4 b) {
    return make_float4(a.x + b.x, a.y + b.y, a.z + b.z, a.w + b.w);
}
__device__ __forceinline__ float4 f4fma(float s, float4 a, float4 acc) {
    return make_float4(fmaf(s, a.x, acc.x), fmaf(s, a.y, acc.y),
                       fmaf(s, a.z, acc.z), fmaf(s, a.w, acc.w));
}
__device__ __forceinline__ float4 f4scale(float4 a, float s) {
    return make_float4(a.x * s, a.y * s, a.z * s, a.w * s);
}
__device__ __forceinline__ uint32_t to_tf32(float x) {
    uint32_t r;
    asm("cvt.rn.tf32.f32 %0, %1;" : "=r"(r) : "f"(x));
    return r;
}
__device__ __forceinline__ float4 tf32_f4(float4 v) {
    return make_float4(__uint_as_float(to_tf32(v.x)), __uint_as_float(to_tf32(v.y)),
                       __uint_as_float(to_tf32(v.z)), __uint_as_float(to_tf32(v.w)));
}
__device__ __forceinline__ void mma_tf32(float c[4], const uint32_t a[4],
                                         const uint32_t b0, const uint32_t b1) {
    asm volatile(
        "mma.sync.aligned.m16n8k8.row.col.f32.tf32.tf32.f32 "
        "{%0,%1,%2,%3}, {%4,%5,%6,%7}, {%8,%9}, {%0,%1,%2,%3};"
        : "+f"(c[0]), "+f"(c[1]), "+f"(c[2]), "+f"(c[3])
        : "r"(a[0]), "r"(a[1]), "r"(a[2]), "r"(a[3]), "r"(b0), "r"(b1));
}

// ---------------------------------------------------------------------------
// Pack W -> g_Wp, tf32, B-fragment order grouped by warp-tile (8 tiles of 32
// cols). u32 index i = ((wt*32 + ks)*32 + lane)*8 + nf*2 + p maps to
//   k = ks*8 + (lane&3) + p*4,  n = wt*32 + nf*8 + (lane>>2)
// so in the GEMM each lane reads its 8 B-values for a kstep as 2 uint4.
// ---------------------------------------------------------------------------
__global__ void __launch_bounds__(256) pack_w_kernel(const float* __restrict__ W)
{
    int idx = blockIdx.x * 1024 + threadIdx.x * 4;  // 64 CTAs cover 65536
    uint32_t v[4];
    #pragma unroll
    for (int e = 0; e < 4; e++) {
        int i = idx + e;
        int p    = i & 1;
        int nf   = (i >> 1) & 3;
        int lane = (i >> 3) & 31;
        int ks   = (i >> 8) & 31;
        int wt   = i >> 13;
        int k = ks * 8 + (lane & 3) + p * 4;
        int n = wt * 32 + nf * 8 + (lane >> 2);
        v[e] = to_tf32(W[k * DMEM + n]);
    }
    *(uint4*)&g_Wp[idx] = make_uint4(v[0], v[1], v[2], v[3]);
}

// ---------------------------------------------------------------------------
// Fused kernel: gather + reduce + tf32 pack + mma GEMM + epilogue.
// Grid = 256 CTAs x 16 rows, 256 threads (8 warps).
// Phase 1: warp w gathers rows 2w, 2w+1 (lane j owns float4 dims j and j+32,
//          no cross-lane reduction). feat stored to smem as tf32, base as f32.
// Phase 2: M=16 x N=256 x K=256 GEMM; warp w owns cols [32w, 32w+32).
//          A-frags: conflict-free LDS (stride 260). B-frags: LDG from g_Wp
//          (L2-resident), fully unrolled for MLP.
// ---------------------------------------------------------------------------
__global__ void __launch_bounds__(256) fused_kernel(
    const float* __restrict__ nodef,   // [N, 128]
    const float* __restrict__ edgef,   // [E, 128]
    const float* __restrict__ mem,     // [N, 256]
    const float* __restrict__ itab,    // [300, 128]
    const float* __restrict__ bbound,  // [301]
    const float* __restrict__ tw,      // [128]
    const float* __restrict__ tbias,   // [128]
    const float* __restrict__ ts,      // [B]
    const float* __restrict__ etimes,  // [B, K]
    const float* __restrict__ ivals,   // [B]
    const float* __restrict__ nivals,  // [B, K]
    const int*   __restrict__ srcn,    // [B]
    const int*   __restrict__ nbr,     // [B, K]
    const int*   __restrict__ eidx,    // [B, K]
    float*       __restrict__ out)     // [B, 256]
{
    __shared__ float s_bb[NBINS + 1];
    __shared__ float s_vf[ROWS * KK];
    __shared__ float s_delta[ROWS * KK];
    __shared__ int   s_m4[ROWS * KK];   // n*64 (float4 idx into mem)
    __shared__ int   s_n4[ROWS * KK];   // n*32
    __shared__ int   s_i4[ROWS * KK];   // bin*32
    __shared__ int   s_e4[ROWS * KK];   // e*32
    __shared__ int   s_src[ROWS];
    __shared__ int   s_sio[ROWS];       // source bin*32
    __shared__ float s_inv[ROWS];
    __shared__ __align__(16) float s_feat[ROWS * FSTR];  // tf32 bits (as float)
    __shared__ __align__(16) float s_base[ROWS * FSTR];

    const int tid  = threadIdx.x;
    const int lane = tid & 31;
    const int wid  = tid >> 5;
    const int r0   = blockIdx.x * ROWS;

    for (int i = tid; i < NBINS + 1; i += 256) s_bb[i] = bbound[i];
    __syncthreads();

    // ---- metadata: 320 (row,k) items
    for (int i = tid; i < ROWS * KK; i += 256) {
        const int row = i / KK;
        int n = nbr[r0 * KK + i];
        int valid = (n != -1);
        int ns = valid ? n : 0;
        s_vf[i] = valid ? 1.0f : 0.0f;
        s_m4[i] = ns * 64;
        s_n4[i] = ns * 32;
        s_e4[i] = eidx[r0 * KK + i] * 32;
        s_delta[i] = ts[r0 + row] - etimes[r0 * KK + i];
        float x = nivals[r0 * KK + i];
        int lo = 0, hi = NBINS + 1;
        while (lo < hi) { int mid = (lo + hi) >> 1; if (s_bb[mid] < x) lo = mid + 1; else hi = mid; }
        s_i4[i] = min(max(lo - 1, 0), NBINS - 1) * 32;
    }
    __syncthreads();

    if (tid < ROWS) {
        float c = 0.f;
        #pragma unroll
        for (int k = 0; k < KK; k++) c += s_vf[tid * KK + k];
        s_inv[tid] = 1.0f / fmaxf(c, 1.0f);
        s_src[tid] = srcn[r0 + tid];
        float x = ivals[r0 + tid];
        int lo = 0, hi = NBINS + 1;
        while (lo < hi) { int mid = (lo + hi) >> 1; if (s_bb[mid] < x) lo = mid + 1; else hi = mid; }
        s_sio[tid] = min(max(lo - 1, 0), NBINS - 1) * 32;
    }
    __syncthreads();

    // ---- phase 1: gather. warp wid handles rows 2*wid and 2*wid+1.
    {
        const float4* __restrict__ mem4   = (const float4*)mem;
        const float4* __restrict__ nodef4 = (const float4*)nodef;
        const float4* __restrict__ itab4  = (const float4*)itab;
        const float4* __restrict__ edgef4 = (const float4*)edgef;
        const float4 w4  = ((const float4*)tw)[lane];
        const float4 tb4 = ((const float4*)tbias)[lane];

        #pragma unroll
        for (int rr = 0; rr < 2; rr++) {
            const int row = wid * 2 + rr;
            const int bi  = row * KK;
            float4 nb0 = make_float4(0.f, 0.f, 0.f, 0.f);
            float4 nb1 = nb0, f0 = nb0, f1 = nb0;

            #pragma unroll
            for (int k = 0; k < KK; k++) {
                const int i = bi + k;
                const float vf = s_vf[i];
                const int m4 = s_m4[i];
                float4 mA = mem4[m4 + lane];
                float4 mB = mem4[m4 + 32 + lane];
                float4 nf = nodef4[s_n4[i] + lane];
                float4 it = itab4[s_i4[i] + lane];
                float4 ef = edgef4[s_e4[i] + lane];
                nb0 = f4fma(vf, f4add(mA, nf), nb0);
                nb1 = f4fma(vf, f4add(mB, it), nb1);
                const float d = s_delta[i];
                f0.x += vf * __cosf(fmaf(d, w4.x, tb4.x));
                f0.y += vf * __cosf(fmaf(d, w4.y, tb4.y));
                f0.z += vf * __cosf(fmaf(d, w4.z, tb4.z));
                f0.w += vf * __cosf(fmaf(d, w4.w, tb4.w));
                f1 = f4fma(vf, ef, f1);
            }

            const float inv = s_inv[row];
            const int s = s_src[row];
            float4 sv0 = f4add(mem4[(size_t)s * 64 + lane], nodef4[(size_t)s * 32 + lane]);
            float4 sv1 = f4add(mem4[(size_t)s * 64 + 32 + lane], itab4[s_sio[row] + lane]);

            float4* fb = (float4*)&s_base[row * FSTR];
            fb[lane]      = f4add(sv0, f4scale(nb0, inv));
            fb[32 + lane] = f4add(sv1, f4scale(nb1, inv));
            float4* ff = (float4*)&s_feat[row * FSTR];
            ff[lane]      = tf32_f4(f4scale(f0, inv));
            ff[32 + lane] = tf32_f4(f4scale(f1, inv));
        }
    }
    __syncthreads();

    // ---- phase 2: GEMM. warp wid owns cols [32*wid, 32*wid+32).
    const int g  = lane >> 2;
    const int tg = lane & 3;

    float acc[4][4];
    #pragma unroll
    for (int nf = 0; nf < 4; nf++)
        #pragma unroll
        for (int q = 0; q < 4; q++) acc[nf][q] = 0.f;

    const uint4* __restrict__ wp4 = ((const uint4*)g_Wp) + wid * 32 * 64;

    #pragma unroll
    for (int ks = 0; ks < 32; ks++) {
        uint4 B01 = wp4[ks * 64 + lane * 2];
        uint4 B23 = wp4[ks * 64 + lane * 2 + 1];
        const int c0 = ks * 8 + tg;
        uint32_t a[4];
        a[0] = __float_as_uint(s_feat[g * FSTR + c0]);
        a[1] = __float_as_uint(s_feat[(g + 8) * FSTR + c0]);
        a[2] = __float_as_uint(s_feat[g * FSTR + c0 + 4]);
        a[3] = __float_as_uint(s_feat[(g + 8) * FSTR + c0 + 4]);
        mma_tf32(acc[0], a, B01.x, B01.y);
        mma_tf32(acc[1], a, B01.z, B01.w);
        mma_tf32(acc[2], a, B23.x, B23.y);
        mma_tf32(acc[3], a, B23.z, B23.w);
    }

    // ---- epilogue: out = base + acc
    #pragma unroll
    for (int nf = 0; nf < 4; nf++) {
        const int c = wid * 32 + nf * 8 + tg * 2;
        float2 o0, o1;
        o0.x = s_base[g * FSTR + c]       + acc[nf][0];
        o0.y = s_base[g * FSTR + c + 1]   + acc[nf][1];
        o1.x = s_base[(g + 8) * FSTR + c]     + acc[nf][2];
        o1.y = s_base[(g + 8) * FSTR + c + 1] + acc[nf][3];
        *(float2*)&out[(r0 + g) * DMEM + c]     = o0;
        *(float2*)&out[(r0 + g + 8) * DMEM + c] = o1;
    }
}

// ---------------------------------------------------------------------------
extern "C" void kernel_launch(void* const* d_in, const int* in_sizes, int n_in,
                              void* d_out, int out_size)
{
    const float* nodef  = (const float*)d_in[0];
    const float* edgef  = (const float*)d_in[1];
    const float* mem    = (const float*)d_in[2];
    const float* itab   = (const float*)d_in[3];
    const float* bbound = (const float*)d_in[4];
    const float* tw     = (const float*)d_in[5];
    const float* tbias  = (const float*)d_in[6];
    const float* Wagg   = (const float*)d_in[7];
    const float* ts     = (const float*)d_in[8];
    const float* etimes = (const float*)d_in[9];
    const float* ivals  = (const float*)d_in[10];
    const float* nivals = (const float*)d_in[11];
    const int*   srcn   = (const int*)d_in[12];
    const int*   nbr    = (const int*)d_in[13];
    const int*   eidx   = (const int*)d_in[14];
    float* out = (float*)d_out;

    pack_w_kernel<<<64, 256>>>(Wagg);
    fused_kernel<<<NCTA, 256>>>(nodef, edgef, mem, itab, bbound, tw, tbias,
                                ts, etimes, ivals, nivals, srcn, nbr, eidx, out);
}